// round 5
// baseline (speedup 1.0000x reference)
#include <cuda_runtime.h>

// RNN-T transducer loss forward. B=16, T=200, U=101, A=512, blank=0.
// Log2-domain anti-diagonal wavefront, TWO diagonals per __syncthreads.
//
//  K1 gather: blk2 = lp[...,0]*log2e, em2[t][u] = lp[b,t,u-1,label[u-1]]*log2e
//     (shifted +1), into [B][T][104] scratch (L2-resident).
//  K2 lattice: 16 CTAs x 128 threads, thread u owns column u.
//     Interval i covers diagonals 2i (cell A, t0=2i-u) and 2i+1 (cell B).
//     alpha[t,u] = lae2(alpha[t-1,u]+blk2[t-1,u], alpha[t,u-1]+em2[t,u])
//     hinA (neighbor's prev-interval B) via shfl_up; warp-boundary lanes via
//     parity-buffered smem (barrier-ordered). hinB (neighbor's A, same
//     interval) via shfl_up; boundary lanes via tagged volatile 64-bit slot.
//     Fixed-order mean reduction in the last-arriving CTA.

#define BQ 16
#define TM 200
#define UM 101
#define AA 512
#define UP 104
#define NEG (-1.0e30f)
#define LOG2E 1.4426950408889634f
#define LN2   0.6931471805599453f

__device__ __align__(16) float g_blk[BQ][TM][UP];
__device__ __align__(16) float g_em [BQ][TM][UP];  // shifted: [t][u] = em[t][u-1]*log2e
__device__ float g_logp[BQ];
__device__ int   g_cnt = 0;

__global__ void tl_gather_kernel(const float* __restrict__ lp,
                                 const int*   __restrict__ labels)
{
    const int total  = BQ * TM * UM;
    const int stride = gridDim.x * blockDim.x;
    int i0 = blockIdx.x * blockDim.x + threadIdx.x;
    #pragma unroll
    for (int kk = 0; kk < 4; ++kk) {
        int i = i0 + kk * stride;
        if (i < total) {
            int u  = i % UM;
            int bt = i / UM;
            int t  = bt % TM;
            int b  = bt / TM;
            int lab = (u < UM - 1) ? __ldg(labels + b * (UM - 1) + u) : 0;
            size_t base = (size_t)i * AA;          // i == ((b*TM + t)*UM + u)
            float bv = __ldg(lp + base);
            float ev = lab ? __ldg(lp + base + lab) : bv;
            g_blk[b][t][u]     = bv * LOG2E;
            g_em [b][t][u + 1] = ev * LOG2E;
            if (u == 0) g_em[b][t][0] = 0.0f;
            if (u == UM - 1) {
                g_blk[b][t][101] = 0.f; g_blk[b][t][102] = 0.f; g_blk[b][t][103] = 0.f;
                g_em [b][t][102] = 0.f; g_em [b][t][103] = 0.f;
            }
        }
    }
}

// logaddexp in log2 domain: returns log2(2^x + 2^y). Exact pass-through for NEG.
__device__ __forceinline__ float lae2(float x, float y)
{
    float m = fmaxf(x, y);
    float d = fminf(x, y) - m;
    return m + __log2f(1.0f + exp2f(d));
}

__global__ __launch_bounds__(128, 1)
void tl_lattice_kernel(const int* __restrict__ Tarr,
                       const int* __restrict__ Uarr,
                       float* __restrict__ out)
{
    extern __shared__ float sm[];
    float* s_blk = sm;                      // [TM][UP]
    float* s_em  = sm + TM * UP;            // [TM][UP]
    __shared__ float s_e[2][4];             // parity-buffered inter-interval B handoff
    __shared__ unsigned long long s_h[3];   // tagged same-interval A handoff

    const int b    = blockIdx.x;
    const int tid  = threadIdx.x;
    const int lane = tid & 31;
    const int w    = tid >> 5;

    // Stage blk/em for this batch into shared (coalesced float4).
    {
        const float4* gb = (const float4*)&g_blk[b][0][0];
        const float4* ge = (const float4*)&g_em [b][0][0];
        float4* sb = (float4*)s_blk;
        float4* se = (float4*)s_em;
        const int n4 = TM * UP / 4;         // 5200
        for (int k = tid; k < n4; k += 128) { sb[k] = gb[k]; se[k] = ge[k]; }
    }
    if (tid < 8) ((float*)s_e)[tid] = NEG;
    if (tid < 3) s_h[tid] = 0ULL;

    const int Tb = __ldg(Tarr + b);
    const int Ub = __ldg(Uarr + b);
    __syncthreads();

    const int u  = tid;
    const int uc = min(u, UP - 1);
    const float* pb = s_blk + uc;           // row stride UP
    const float* pe = s_em  + uc;

    const int smax = (Tb - 1) + Ub;
    const int nint = (smax + 2) >> 1;       // intervals of 2 diagonals

    float own   = 0.0f;                     // alpha at this thread's last active diag
    float lastB = NEG;                      // raw cell-B value of previous interval
    volatile unsigned long long* hp = (w > 0) ? &s_h[w - 1] : 0;

    for (int i = 0; i < nint; ++i) {
        const int t0  = 2 * i - u;
        const int t1  = t0 + 1;
        const int par = i & 1;

        // static-operand loads (clamped; off the dependency chain)
        const int tApb = min(max(t0, 1), Tb - 1);
        const int tAem = min(max(t0, 0), Tb - 1);
        const int tBpb = min(max(t1, 1), Tb - 1);
        const int tBem = min(max(t1, 0), Tb - 1);
        const float blkA = pb[(tApb - 1) * UP];
        const float emA  = pe[ tAem      * UP];
        const float blkB = pb[(tBpb - 1) * UP];
        const float emB  = pe[ tBem      * UP];

        // ---- cell A (diag 2i): alpha[t0][u] ----
        float hinA = __shfl_up_sync(0xffffffffu, lastB, 1);
        if (lane == 0) hinA = (w > 0) ? s_e[par ^ 1][w - 1] : NEG;
        const float horA = hinA + emA;
        const float verA = own + blkA;
        const float lvA  = lae2(verA, horA);
        const float valA = (t0 == 0) ? ((u == 0) ? 0.0f : horA) : lvA;

        // same-interval boundary handoff of valA (tagged; barrier keeps warps
        // phase-aligned so the poll almost never iterates)
        if (lane == 31 && w < 3)
            s_h[w] = ((unsigned long long)(unsigned)(i + 1) << 32)
                     | (unsigned long long)__float_as_uint(valA);

        // ---- cell B (diag 2i+1): alpha[t1][u] ----
        float hinB = __shfl_up_sync(0xffffffffu, valA, 1);
        if (lane == 0) {
            if (w > 0) {
                unsigned long long v = *hp;
                while ((unsigned)(v >> 32) != (unsigned)(i + 1)) v = *hp;
                hinB = __uint_as_float((unsigned)v);
            } else {
                hinB = NEG;
            }
        }
        const float horB = hinB + emB;
        const float verB = valA + blkB;
        const float lvB  = lae2(verB, horB);
        const float valB = (t1 == 0) ? ((u == 0) ? 0.0f : horB) : lvB;

        // commit (activity-gated own; raw lastB is consumed only by cells
        // that are themselves inactive whenever this one was)
        own   = ((unsigned)t0 < (unsigned)Tb) ? valA : own;
        own   = ((unsigned)t1 < (unsigned)Tb) ? valB : own;
        lastB = valB;

        if (lane == 31 && w < 3) s_e[par][w] = valB;   // read next interval (par^1 flips)
        __syncthreads();
    }

    // log_p = (alpha2[Tb-1][Ub] + blk2[Tb-1][Ub]) * ln2
    if (u == Ub) g_logp[b] = (own + s_blk[(Tb - 1) * UP + Ub]) * LN2;
    __syncthreads();

    // Fixed-order mean reduction in the last-arriving CTA (deterministic).
    if (tid == 0) {
        __threadfence();
        int old = atomicAdd(&g_cnt, 1);
        if (old == BQ - 1) {
            __threadfence();
            float ssum = 0.0f;
            #pragma unroll
            for (int i2 = 0; i2 < BQ; ++i2) ssum += g_logp[i2];
            out[0] = -ssum / (float)BQ;
            g_cnt = 0;                      // reset for next graph replay
        }
    }
}

extern "C" void kernel_launch(void* const* d_in, const int* in_sizes, int n_in,
                              void* d_out, int out_size)
{
    const float* lp     = (const float*)d_in[0];
    const int*   labels = (const int*)  d_in[1];
    const int*   Tarr   = (const int*)  d_in[2];
    const int*   Uarr   = (const int*)  d_in[3];
    float* out = (float*)d_out;

    const int smem_bytes = 2 * TM * UP * (int)sizeof(float);   // 166,400
    cudaFuncSetAttribute(tl_lattice_kernel,
                         cudaFuncAttributeMaxDynamicSharedMemorySize,
                         smem_bytes);

    const int total  = BQ * TM * UM;                           // 323,200
    const int blocks = (total + 256 * 4 - 1) / (256 * 4);      // 316
    tl_gather_kernel<<<blocks, 256>>>(lp, labels);
    tl_lattice_kernel<<<BQ, 128, smem_bytes>>>(Tarr, Uarr, out);
}

// round 6
// speedup vs baseline: 1.1566x; 1.1566x over previous
#include <cuda_runtime.h>

// RNN-T transducer loss. B=16, T=200, U=101, A=512, blank=0.
// Forward/backward split lattice, log2 domain, raw MUFU lae.
//   alpha rows [0,ts), beta rows [ts,Tb), ts = (Tb+1)/2, run concurrently by
//   warps 0-3 / 4-7 of one CTA; join: log_p = LSE_u(alpha[ts-1,u]+blk[ts-1,u]+beta[ts,u]).

#define BQ 16
#define TM 200
#define UM 101
#define AA 512
#define UP 104
#define NEG (-1.0e30f)
#define LOG2E 1.4426950408889634f
#define LN2   0.6931471805599453f

__device__ __align__(16) float g_blk[BQ][TM][UP];
__device__ __align__(16) float g_em [BQ][TM][UP];  // shifted: [t][u] = em[t][u-1]*log2e
__device__ float g_logp[BQ];
__device__ int   g_cnt = 0;

__global__ void tl_gather_kernel(const float* __restrict__ lp,
                                 const int*   __restrict__ labels)
{
    const int total  = BQ * TM * UM;
    const int stride = gridDim.x * blockDim.x;
    int i0 = blockIdx.x * blockDim.x + threadIdx.x;
    #pragma unroll
    for (int kk = 0; kk < 4; ++kk) {
        int i = i0 + kk * stride;
        if (i < total) {
            int u  = i % UM;
            int bt = i / UM;
            int t  = bt % TM;
            int b  = bt / TM;
            int lab = (u < UM - 1) ? __ldg(labels + b * (UM - 1) + u) : 0;
            size_t base = (size_t)i * AA;
            float bv = __ldg(lp + base);
            float ev = lab ? __ldg(lp + base + lab) : bv;
            g_blk[b][t][u]     = bv * LOG2E;
            g_em [b][t][u + 1] = ev * LOG2E;
            if (u == 0) g_em[b][t][0] = 0.0f;
            if (u == UM - 1) {
                g_blk[b][t][101] = 0.f; g_blk[b][t][102] = 0.f; g_blk[b][t][103] = 0.f;
                g_em [b][t][102] = 0.f; g_em [b][t][103] = 0.f;
            }
        }
    }
}

__device__ __forceinline__ float ex2(float x) { float y; asm("ex2.approx.f32 %0, %1;" : "=f"(y) : "f"(x)); return y; }
__device__ __forceinline__ float lg2(float x) { float y; asm("lg2.approx.f32 %0, %1;" : "=f"(y) : "f"(x)); return y; }

// log2(2^x + 2^y); exact pass-through when one arg is NEG (ex2(-huge)=0).
__device__ __forceinline__ float lae2(float x, float y)
{
    float m = fmaxf(x, y);
    float d = fminf(x, y) - m;
    return m + lg2(1.0f + ex2(d));
}

__global__ __launch_bounds__(256, 1)
void tl_lattice_kernel(const int* __restrict__ Tarr,
                       const int* __restrict__ Uarr,
                       float* __restrict__ out)
{
    extern __shared__ float sm[];
    float* s_blk = sm;                  // [TM][UP]
    float* s_em  = sm + TM * UP;        // [TM][UP]
    __shared__ float s_eF[2][132];      // forward edge (slot 0 pinned NEG)
    __shared__ float s_eB[2][132];      // backward edge (slot 0 pinned NEG)
    __shared__ float s_ja[UP], s_jb[UP];

    const int b   = blockIdx.x;
    const int tid = threadIdx.x;

    {   // stage blk/em (coalesced float4, 8 warps)
        const float4* gb = (const float4*)&g_blk[b][0][0];
        const float4* ge = (const float4*)&g_em [b][0][0];
        float4* sb = (float4*)s_blk;
        float4* se = (float4*)s_em;
        const int n4 = TM * UP / 4;     // 5200
        for (int k = tid; k < n4; k += 256) { sb[k] = gb[k]; se[k] = ge[k]; }
    }
    for (int k = tid; k < 2 * 132; k += 256) { ((float*)s_eF)[k] = NEG; ((float*)s_eB)[k] = NEG; }
    if (tid < UP) { s_jb[tid] = 0.0f; s_ja[tid] = NEG; }

    const int Tb = __ldg(Tarr + b);
    const int Ub = __ldg(Uarr + b);
    const int ts = (Tb + 1) >> 1;                 // forward owns rows [0,ts)
    const int nbk = Tb - ts;                      // backward owns rows [ts,Tb)
    __syncthreads();

    const int smax_f = (ts - 1) + Ub;
    const int smax_b = (nbk - 1) + Ub;
    const int nsteps = (smax_f > smax_b ? smax_f : smax_b) + 1;

    const bool fwd = (tid < 128);
    const int  u   = fwd ? tid : 0;               // forward column
    const int  v   = fwd ? 0 : (tid - 128);       // backward diag index; col = Ub - v
    const int  ucf = min(tid, 103);
    const int  ucb = min(max(Ub - (tid - 128), 0), 103);
    const float seedB = s_blk[(Tb - 1) * UP + Ub];

    float own = 0.0f;

    for (int s = 0; s < nsteps; ++s) {
        const int w = s & 1;
        const int r = w ^ 1;

        if (fwd) {
            const int t   = s - u;
            const int tc  = min(max(t, 0), ts - 1);
            const int tc1 = min(max(t, 1), ts - 1);
            const float hin  = s_eF[r][u];
            const float emv  = s_em [ tc       * UP + ucf];
            const float blkv = s_blk[(tc1 - 1) * UP + ucf];
            const float ver = own + blkv;
            const float hor = hin + emv;
            const float lv  = lae2(ver, hor);
            const float val = (t == 0) ? ((u == 0) ? 0.0f : hor) : lv;
            own = ((unsigned)t < (unsigned)ts) ? val : own;
            s_eF[w][u + 1] = val;
        } else {
            const int t   = (Tb - 1) - (s - v);   // row, counts down
            const int tcb = min(max(t, ts), Tb - 1);
            const float hin  = s_eB[r][v];
            const float emv  = s_em [tcb * UP + ucb + 1];   // em[t][u]
            const float blkv = s_blk[tcb * UP + ucb];       // blk[t][u]
            const float ver = own + blkv;
            const float hor = hin + emv;
            const float lv  = lae2(ver, hor);
            const float val = (t == Tb - 1) ? ((v == 0) ? seedB : hor) : lv;
            own = ((unsigned)(s - v) < (unsigned)nbk) ? val : own;
            s_eB[w][v + 1] = val;
        }
        __syncthreads();
    }

    // junction row: log_p = LSE_u(alpha[ts-1,u] + blk[ts-1,u] + beta[ts,u])
    if (fwd) {
        if (u < UP) s_ja[u] = (u <= Ub) ? own + s_blk[(ts - 1) * UP + u] : NEG;
    } else {
        const int uu = Ub - v;
        if (uu >= 0) s_jb[uu] = own;
    }
    __syncthreads();

    if (tid < 32) {
        float x0 = (tid      < UP) ? s_ja[tid]      + s_jb[tid]      : NEG;
        float x1 = (tid + 32 < UP) ? s_ja[tid + 32] + s_jb[tid + 32] : NEG;
        float x2 = (tid + 64 < UP) ? s_ja[tid + 64] + s_jb[tid + 64] : NEG;
        float x3 = (tid + 96 < UP) ? s_ja[tid + 96] + s_jb[tid + 96] : NEG;
        float m = fmaxf(fmaxf(x0, x1), fmaxf(x2, x3));
        #pragma unroll
        for (int o = 16; o > 0; o >>= 1)
            m = fmaxf(m, __shfl_xor_sync(0xffffffffu, m, o));
        float sum2 = ex2(x0 - m) + ex2(x1 - m) + ex2(x2 - m) + ex2(x3 - m);
        #pragma unroll
        for (int o = 16; o > 0; o >>= 1)
            sum2 += __shfl_xor_sync(0xffffffffu, sum2, o);
        if (tid == 0) g_logp[b] = (m + lg2(sum2)) * LN2;
    }
    __syncthreads();

    // fixed-order mean reduction in the last-arriving CTA (deterministic)
    if (tid == 0) {
        __threadfence();
        int old = atomicAdd(&g_cnt, 1);
        if (old == BQ - 1) {
            __threadfence();
            float ssum = 0.0f;
            #pragma unroll
            for (int i = 0; i < BQ; ++i) ssum += g_logp[i];
            out[0] = -ssum / (float)BQ;
            g_cnt = 0;                  // reset for next graph replay
        }
    }
}

extern "C" void kernel_launch(void* const* d_in, const int* in_sizes, int n_in,
                              void* d_out, int out_size)
{
    const float* lp     = (const float*)d_in[0];
    const int*   labels = (const int*)  d_in[1];
    const int*   Tarr   = (const int*)  d_in[2];
    const int*   Uarr   = (const int*)  d_in[3];
    float* out = (float*)d_out;

    const int smem_bytes = 2 * TM * UP * (int)sizeof(float);   // 166,400
    cudaFuncSetAttribute(tl_lattice_kernel,
                         cudaFuncAttributeMaxDynamicSharedMemorySize,
                         smem_bytes);

    const int total  = BQ * TM * UM;
    const int blocks = (total + 256 * 4 - 1) / (256 * 4);      // 316
    tl_gather_kernel<<<blocks, 256>>>(lp, labels);
    tl_lattice_kernel<<<BQ, 256, smem_bytes>>>(Tarr, Uarr, out);
}

// round 7
// speedup vs baseline: 1.1635x; 1.0060x over previous
#include <cuda_runtime.h>

// RNN-T transducer loss. B=16, T=200, U=101, A=512, blank=0.
// Barrier-free split lattice: warp 0 = forward rows [0,ts), warp 1 = backward
// rows [ts,Tb) (reversed coords), both with interleaved column ownership:
// lane k owns columns {k, k+32, k+64, k+96}; cell (t,u) runs at step s=t+u,
// so every horizontal dependency is a previous-step value of lane k-1 ->
// 4 rotated shfls per step, no __syncthreads, no smem on the chain.
// Join: log_p = LSE_u(alpha[ts-1,u] + blk[ts-1,u] + beta[ts,u]).

#define BQ 16
#define TM 200
#define UM 101
#define AA 512
#define UP 104
#define NEG (-1.0e30f)
#define LOG2E 1.4426950408889634f
#define LN2   0.6931471805599453f
#define FULL  0xffffffffu

__device__ __align__(16) float g_blk[BQ][TM][UP];
__device__ __align__(16) float g_em [BQ][TM][UP];  // shifted: [t][u] = em[t][u-1]*log2e, [t][0]=0
__device__ float g_logp[BQ];
__device__ int   g_cnt = 0;

__global__ void tl_gather_kernel(const float* __restrict__ lp,
                                 const int*   __restrict__ labels)
{
    const int total  = BQ * TM * UM;
    const int stride = gridDim.x * blockDim.x;
    int i0 = blockIdx.x * blockDim.x + threadIdx.x;
    #pragma unroll
    for (int kk = 0; kk < 4; ++kk) {
        int i = i0 + kk * stride;
        if (i < total) {
            int u  = i % UM;
            int bt = i / UM;
            int t  = bt % TM;
            int b  = bt / TM;
            int lab = (u < UM - 1) ? __ldg(labels + b * (UM - 1) + u) : 0;
            size_t base = (size_t)i * AA;
            float bv = __ldg(lp + base);
            float ev = lab ? __ldg(lp + base + lab) : bv;
            g_blk[b][t][u]     = bv * LOG2E;
            g_em [b][t][u + 1] = ev * LOG2E;
            if (u == 0) g_em[b][t][0] = 0.0f;
            if (u == UM - 1) {
                g_blk[b][t][101] = 0.f; g_blk[b][t][102] = 0.f; g_blk[b][t][103] = 0.f;
                g_em [b][t][102] = 0.f; g_em [b][t][103] = 0.f;
            }
        }
    }
}

__device__ __forceinline__ float ex2(float x) { float y; asm("ex2.approx.f32 %0, %1;" : "=f"(y) : "f"(x)); return y; }
__device__ __forceinline__ float lg2(float x) { float y; asm("lg2.approx.f32 %0, %1;" : "=f"(y) : "f"(x)); return y; }

// log2(2^x + 2^y); exact pass-through when one arg is NEG.
__device__ __forceinline__ float lae2(float x, float y)
{
    float m = fmaxf(x, y);
    float d = fminf(x, y) - m;
    return m + lg2(1.0f + ex2(d));
}

__global__ __launch_bounds__(256, 1)
void tl_lattice_kernel(const int* __restrict__ Tarr,
                       const int* __restrict__ Uarr,
                       float* __restrict__ out)
{
    extern __shared__ float sm[];
    float* s_blk = sm;                  // [TM][UP], log2 domain
    float* s_em  = sm + TM * UP;        // [TM][UP]
    __shared__ float s_ja[UP], s_jb[UP];

    const int b    = blockIdx.x;
    const int tid  = threadIdx.x;
    const int lane = tid & 31;
    const int wid  = tid >> 5;

    {   // stage blk/em (coalesced float4, 8 warps)
        const float4* gb = (const float4*)&g_blk[b][0][0];
        const float4* ge = (const float4*)&g_em [b][0][0];
        float4* sb = (float4*)s_blk;
        float4* se = (float4*)s_em;
        const int n4 = TM * UP / 4;     // 5200
        for (int k = tid; k < n4; k += 256) { sb[k] = gb[k]; se[k] = ge[k]; }
    }
    if (tid < UP) { s_ja[tid] = NEG; s_jb[tid] = 0.0f; }

    const int Tb  = __ldg(Tarr + b);
    const int Ub  = __ldg(Uarr + b);
    const int ts  = (Tb + 1) >> 1;      // forward owns rows [0,ts)
    const int nbk = Tb - ts;            // backward owns rows [ts,Tb)
    __syncthreads();

    const int src = (lane + 31) & 31;   // rotate-up source lane

    if (wid == 0) {
        // ---------------- forward: alpha over rows [0, ts) ----------------
        const int R = ts;
        const int nsteps = R + Ub;      // last cell (R-1, Ub) at step R-1+Ub
        float h[4] = {0.f, 0.f, 0.f, 0.f};

        for (int s = 0; s < nsteps; ++s) {
            float r0 = __shfl_sync(FULL, h[0], src);
            float r1 = __shfl_sync(FULL, h[1], src);
            float r2 = __shfl_sync(FULL, h[2], src);
            float r3 = __shfl_sync(FULL, h[3], src);
            float hin[4];
            hin[0] = lane ? r0 : NEG;
            hin[1] = lane ? r1 : r0;
            hin[2] = lane ? r2 : r1;
            hin[3] = lane ? r3 : r2;
            #pragma unroll
            for (int j = 0; j < 4; ++j) {
                const int u  = lane + 32 * j;
                const int t  = s - u;
                const int tc = min(max(t, 0), R - 1);
                const int uc = min(u, UP - 1);
                const float emv  = s_em [ tc              * UP + uc];
                const float blkv = s_blk[ max(tc - 1, 0)  * UP + uc];
                const float hor = hin[j] + emv;
                const float ver = h[j]   + blkv;
                const float lv  = lae2(ver, hor);
                const float val = (t == 0) ? ((u == 0) ? 0.0f : hor) : lv;
                h[j] = ((unsigned)t < (unsigned)R) ? val : h[j];
            }
        }
        // junction row ts-1: ja[u] = alpha[ts-1,u] + blk[ts-1,u]
        #pragma unroll
        for (int j = 0; j < 4; ++j) {
            const int u = lane + 32 * j;
            if (u <= Ub) s_ja[u] = h[j] + s_blk[(R - 1) * UP + u];
        }
    } else if (wid == 1) {
        // ---------------- backward: beta over rows [ts, Tb) ----------------
        // coords: v = Ub-u, t' = Tb-1-t; beta'[t',v] mirrors the forward shape.
        const int R = nbk;
        const int nsteps = R + Ub;
        const float seedB = s_blk[(Tb - 1) * UP + Ub];
        float h[4] = {0.f, 0.f, 0.f, 0.f};

        for (int s = 0; s < nsteps; ++s) {
            float r0 = __shfl_sync(FULL, h[0], src);
            float r1 = __shfl_sync(FULL, h[1], src);
            float r2 = __shfl_sync(FULL, h[2], src);
            float r3 = __shfl_sync(FULL, h[3], src);
            float hin[4];
            hin[0] = lane ? r0 : NEG;
            hin[1] = lane ? r1 : r0;
            hin[2] = lane ? r2 : r1;
            hin[3] = lane ? r3 : r2;
            #pragma unroll
            for (int j = 0; j < 4; ++j) {
                const int v   = lane + 32 * j;
                const int tp  = s - v;
                const int tpc = min(max(tp, 0), R - 1);
                const int t   = Tb - 1 - tpc;            // real row
                const int u   = Ub - v;
                const int uc  = min(max(u, 0), UP - 1);
                const float emv  = s_em [t * UP + min(uc + 1, UP - 1)];  // emit[t][u]
                const float blkv = s_blk[t * UP + uc];                   // blk[t][u]
                const float hor = hin[j] + emv;
                const float ver = h[j]   + blkv;
                const float lv  = lae2(ver, hor);
                const float val = (tp == 0) ? ((v == 0) ? seedB : hor) : lv;
                h[j] = ((unsigned)tp < (unsigned)R) ? val : h[j];
            }
        }
        // junction row ts: jb[u] = beta[ts, u]
        #pragma unroll
        for (int j = 0; j < 4; ++j) {
            const int u = Ub - (lane + 32 * j);
            if (u >= 0) s_jb[u] = h[j];
        }
    }
    __syncthreads();

    // log_p = LSE2_u(ja[u] + jb[u]) * ln2   (warp 0)
    if (tid < 32) {
        float x0 = (tid      < UP) ? s_ja[tid]      + s_jb[tid]      : NEG;
        float x1 = (tid + 32 < UP) ? s_ja[tid + 32] + s_jb[tid + 32] : NEG;
        float x2 = (tid + 64 < UP) ? s_ja[tid + 64] + s_jb[tid + 64] : NEG;
        float x3 = (tid + 96 < UP) ? s_ja[tid + 96] + s_jb[tid + 96] : NEG;
        float m = fmaxf(fmaxf(x0, x1), fmaxf(x2, x3));
        #pragma unroll
        for (int o = 16; o > 0; o >>= 1)
            m = fmaxf(m, __shfl_xor_sync(FULL, m, o));
        float sum2 = ex2(x0 - m) + ex2(x1 - m) + ex2(x2 - m) + ex2(x3 - m);
        #pragma unroll
        for (int o = 16; o > 0; o >>= 1)
            sum2 += __shfl_xor_sync(FULL, sum2, o);
        if (tid == 0) g_logp[b] = (m + lg2(sum2)) * LN2;
    }
    __syncthreads();

    // fixed-order mean reduction in the last-arriving CTA (deterministic)
    if (tid == 0) {
        __threadfence();
        int old = atomicAdd(&g_cnt, 1);
        if (old == BQ - 1) {
            __threadfence();
            float ssum = 0.0f;
            #pragma unroll
            for (int i = 0; i < BQ; ++i) ssum += g_logp[i];
            out[0] = -ssum / (float)BQ;
            g_cnt = 0;                  // reset for next graph replay
        }
    }
}

extern "C" void kernel_launch(void* const* d_in, const int* in_sizes, int n_in,
                              void* d_out, int out_size)
{
    const float* lp     = (const float*)d_in[0];
    const int*   labels = (const int*)  d_in[1];
    const int*   Tarr   = (const int*)  d_in[2];
    const int*   Uarr   = (const int*)  d_in[3];
    float* out = (float*)d_out;

    const int smem_bytes = 2 * TM * UP * (int)sizeof(float);   // 166,400
    cudaFuncSetAttribute(tl_lattice_kernel,
                         cudaFuncAttributeMaxDynamicSharedMemorySize,
                         smem_bytes);

    const int total  = BQ * TM * UM;
    const int blocks = (total + 256 * 4 - 1) / (256 * 4);      // 316
    tl_gather_kernel<<<blocks, 256>>>(lp, labels);
    tl_lattice_kernel<<<BQ, 256, smem_bytes>>>(Tarr, Uarr, out);
}

// round 8
// speedup vs baseline: 1.3825x; 1.1882x over previous
#include <cuda_runtime.h>

// RNN-T transducer loss. B=16, T=200, U=101, A=512, blank=0.
// LINEAR-domain split lattice (FFMA recurrence), r7's proven barrier-free
// schedule: warp0 = alpha rows [0,ts), warp1 = beta rows [ts,Tb) reversed;
// lane k owns columns {k,k+32,k+64,k+96}; neighbor via rotated shfl.
//   stored[t,u] = true[t,u] * 2^(10*(t+u)(+1 for beta)) * 2^(Ecorr)
// scale baked into tables (gather: pb=2^(lp*log2e+10)) + warp-uniform
// correction every 16 steps. Junction: log_p = LSE_u(ja[u]+jb[u]).

#define BQ 16
#define TM 200
#define UM 101
#define AA 512
#define UP 104
#define NEG (-1.0e30f)
#define LOG2E 1.4426950408889634f
#define LN2   0.6931471805599453f
#define FULL  0xffffffffu
#define CF    10.0f        // bits of boost per table application
#define TGT   157          // rescale target biased exponent (2^30)

__device__ __align__(16) float g_pb[BQ][TM][UP];
__device__ __align__(16) float g_pe[BQ][TM][UP];   // shifted: [t][u] = 2^(emit2[t][u-1]+CF), [t][0]=0
__device__ float g_logp[BQ];
__device__ int   g_cnt = 0;

__device__ __forceinline__ float ex2(float x) { float y; asm("ex2.approx.f32 %0, %1;" : "=f"(y) : "f"(x)); return y; }
__device__ __forceinline__ float lg2(float x) { float y; asm("lg2.approx.f32 %0, %1;" : "=f"(y) : "f"(x)); return y; }

__global__ void tl_gather_kernel(const float* __restrict__ lp,
                                 const int*   __restrict__ labels)
{
    const int total  = BQ * TM * UM;
    const int stride = gridDim.x * blockDim.x;
    int i0 = blockIdx.x * blockDim.x + threadIdx.x;
    #pragma unroll
    for (int kk = 0; kk < 4; ++kk) {
        int i = i0 + kk * stride;
        if (i < total) {
            int u  = i % UM;
            int bt = i / UM;
            int t  = bt % TM;
            int b  = bt / TM;
            int lab = (u < UM - 1) ? __ldg(labels + b * (UM - 1) + u) : 0;
            size_t base = (size_t)i * AA;
            float bv = __ldg(lp + base);
            float ev = lab ? __ldg(lp + base + lab) : bv;
            g_pb[b][t][u]     = ex2(fmaf(bv, LOG2E, CF));
            g_pe[b][t][u + 1] = ex2(fmaf(ev, LOG2E, CF));
            if (u == 0) g_pe[b][t][0] = 0.0f;
            if (u == UM - 1) {
                g_pb[b][t][101] = 0.f; g_pb[b][t][102] = 0.f; g_pb[b][t][103] = 0.f;
                g_pe[b][t][102] = 0.f; g_pe[b][t][103] = 0.f;
            }
        }
    }
}

// Warp-uniform power-of-two renormalization; Ec accumulates applied bits.
__device__ __forceinline__ void rescale4(float h[4], int& Ec)
{
    float m = fmaxf(fmaxf(h[0], h[1]), fmaxf(h[2], h[3]));
    #pragma unroll
    for (int o = 16; o > 0; o >>= 1)
        m = fmaxf(m, __shfl_xor_sync(FULL, m, o));
    int ex = (__float_as_int(m) >> 23) & 255;
    int k  = TGT - ex;
    k = max(-126, min(126, k));
    float f = __int_as_float((k + 127) << 23);
    #pragma unroll
    for (int j = 0; j < 4; ++j) h[j] *= f;
    Ec += k;
}

__global__ __launch_bounds__(256, 1)
void tl_lattice_kernel(const int* __restrict__ Tarr,
                       const int* __restrict__ Uarr,
                       float* __restrict__ out)
{
    extern __shared__ float sm[];
    float* s_pb = sm;                  // [TM][UP] linear, boosted by 2^CF
    float* s_pe = sm + TM * UP;        // [TM][UP]
    __shared__ float s_ja[UP], s_jb[UP];

    const int b    = blockIdx.x;
    const int tid  = threadIdx.x;
    const int lane = tid & 31;
    const int wid  = tid >> 5;

    {   // stage (coalesced float4, 8 warps)
        const float4* gb = (const float4*)&g_pb[b][0][0];
        const float4* ge = (const float4*)&g_pe[b][0][0];
        float4* sb = (float4*)s_pb;
        float4* se = (float4*)s_pe;
        const int n4 = TM * UP / 4;    // 5200
        for (int k = tid; k < n4; k += 256) { sb[k] = gb[k]; se[k] = ge[k]; }
    }
    if (tid < UP) { s_ja[tid] = NEG; s_jb[tid] = 0.0f; }

    const int Tb  = __ldg(Tarr + b);
    const int Ub  = __ldg(Uarr + b);
    const int ts  = (Tb + 1) >> 1;     // alpha rows [0,ts), beta rows [ts,Tb)
    const int nbk = Tb - ts;
    __syncthreads();

    const int src = (lane + 31) & 31;  // rotate-up source

    if (wid == 0) {
        // ---- forward alpha, rows [0, ts) ----
        const int R = ts;
        const int nsteps = R + Ub;
        int uu[4], uc[4];
        #pragma unroll
        for (int j = 0; j < 4; ++j) { uu[j] = lane + 32 * j; uc[j] = min(uu[j], UP - 1); }
        float h[4] = {(lane == 0) ? 1.0f : 0.0f, 0.f, 0.f, 0.f};
        int Ec = 0;

        for (int s = 1; s < nsteps; ++s) {
            float r0 = __shfl_sync(FULL, h[0], src);
            float r1 = __shfl_sync(FULL, h[1], src);
            float r2 = __shfl_sync(FULL, h[2], src);
            float r3 = __shfl_sync(FULL, h[3], src);
            float hin[4];
            hin[0] = lane ? r0 : 0.0f;
            hin[1] = lane ? r1 : r0;
            hin[2] = lane ? r2 : r1;
            hin[3] = lane ? r3 : r2;
            #pragma unroll
            for (int j = 0; j < 4; ++j) {
                const int t  = s - uu[j];
                const int c  = max(t, 0);          // em row (t clamped)
                const int cm = max(t - 1, 0);      // pb row (t-1 clamped)
                const float pev = s_pe[c  * UP + uc[j]];
                const float pbv = s_pb[cm * UP + uc[j]];
                const float val = fmaf(h[j], pbv, hin[j] * pev);
                h[j] = (t < R) ? val : h[j];       // freeze at t==R-1
            }
            if ((s & 15) == 0) rescale4(h, Ec);
        }
        // junction: ja[u] = log2(alpha[ts-1,u]) + log2(blk[ts-1,u])
        #pragma unroll
        for (int j = 0; j < 4; ++j) {
            const int u = uu[j];
            if (u <= Ub) {
                const float pbJ = s_pb[(R - 1) * UP + u];
                s_ja[u] = lg2(h[j]) - CF * (float)(R - 1 + u) - (float)Ec
                        + lg2(pbJ) - CF;
            }
        }
    } else if (wid == 1) {
        // ---- backward beta, rows [ts, Tb); coords tp=Tb-1-t, v=Ub-u ----
        const int R = nbk;
        const int nsteps = R + Ub;
        const float seed = s_pb[(Tb - 1) * UP + Ub];   // = 2^(blk2_term + CF)
        int vv[4], cpe[4], cpb[4];
        #pragma unroll
        for (int j = 0; j < 4; ++j) {
            vv[j] = lane + 32 * j;
            int u = max(Ub - vv[j], 0);
            cpb[j] = u;                  // blk col u
            cpe[j] = u + 1;              // emit col u (shifted table), <=101
        }
        float h[4] = {(lane == 0) ? seed : 0.0f, 0.f, 0.f, 0.f};
        int Ec = 0;

        for (int s = 1; s < nsteps; ++s) {
            float r0 = __shfl_sync(FULL, h[0], src);
            float r1 = __shfl_sync(FULL, h[1], src);
            float r2 = __shfl_sync(FULL, h[2], src);
            float r3 = __shfl_sync(FULL, h[3], src);
            float hin[4];
            hin[0] = lane ? r0 : 0.0f;
            hin[1] = lane ? r1 : r0;
            hin[2] = lane ? r2 : r1;
            hin[3] = lane ? r3 : r2;
            #pragma unroll
            for (int j = 0; j < 4; ++j) {
                const int tp  = s - vv[j];
                const int c   = min(max(tp, 0), R - 1);
                const int row = (Tb - 1) - c;
                const float pev = s_pe[row * UP + cpe[j]];
                const float pbv = s_pb[row * UP + cpb[j]];
                const float val = fmaf(h[j], pbv, hin[j] * pev);
                h[j] = (tp < R) ? val : h[j];
            }
            if ((s & 15) == 0) rescale4(h, Ec);
        }
        // junction: jb[u] = log2(beta[ts,u]); stored = true*2^(CF*(tp+v+1)+Ec)
        #pragma unroll
        for (int j = 0; j < 4; ++j) {
            const int u = Ub - vv[j];
            if (u >= 0)
                s_jb[u] = lg2(h[j]) - CF * (float)(R - 1 + vv[j] + 1) - (float)Ec;
        }
    }
    __syncthreads();

    // log_p = LN2 * LSE2_u(ja[u] + jb[u])   (warp 0)
    if (tid < 32) {
        float x0 = (tid      < UP) ? s_ja[tid]      + s_jb[tid]      : NEG;
        float x1 = (tid + 32 < UP) ? s_ja[tid + 32] + s_jb[tid + 32] : NEG;
        float x2 = (tid + 64 < UP) ? s_ja[tid + 64] + s_jb[tid + 64] : NEG;
        float x3 = (tid + 96 < UP) ? s_ja[tid + 96] + s_jb[tid + 96] : NEG;
        float m = fmaxf(fmaxf(x0, x1), fmaxf(x2, x3));
        #pragma unroll
        for (int o = 16; o > 0; o >>= 1)
            m = fmaxf(m, __shfl_xor_sync(FULL, m, o));
        float sum2 = ex2(x0 - m) + ex2(x1 - m) + ex2(x2 - m) + ex2(x3 - m);
        #pragma unroll
        for (int o = 16; o > 0; o >>= 1)
            sum2 += __shfl_xor_sync(FULL, sum2, o);
        if (tid == 0) g_logp[b] = (m + lg2(sum2)) * LN2;
    }
    __syncthreads();

    // fixed-order mean reduction in the last-arriving CTA (deterministic)
    if (tid == 0) {
        __threadfence();
        int old = atomicAdd(&g_cnt, 1);
        if (old == BQ - 1) {
            __threadfence();
            float ssum = 0.0f;
            #pragma unroll
            for (int i = 0; i < BQ; ++i) ssum += g_logp[i];
            out[0] = -ssum / (float)BQ;
            g_cnt = 0;                 // reset for next graph replay
        }
    }
}

extern "C" void kernel_launch(void* const* d_in, const int* in_sizes, int n_in,
                              void* d_out, int out_size)
{
    const float* lp     = (const float*)d_in[0];
    const int*   labels = (const int*)  d_in[1];
    const int*   Tarr   = (const int*)  d_in[2];
    const int*   Uarr   = (const int*)  d_in[3];
    float* out = (float*)d_out;

    const int smem_bytes = 2 * TM * UP * (int)sizeof(float);   // 166,400
    cudaFuncSetAttribute(tl_lattice_kernel,
                         cudaFuncAttributeMaxDynamicSharedMemorySize,
                         smem_bytes);

    const int total  = BQ * TM * UM;
    const int blocks = (total + 256 * 4 - 1) / (256 * 4);      // 316
    tl_gather_kernel<<<blocks, 256>>>(lp, labels);
    tl_lattice_kernel<<<BQ, 256, smem_bytes>>>(Tarr, Uarr, out);
}